// round 2
// baseline (speedup 1.0000x reference)
#include <cuda_runtime.h>

#define NB 2
#define NS 2048
#define ND 1024
#define NH 16
#define HD 64
#define NR 129   // 2*64+1 relative buckets

// scratch (allocation-free rule: device globals)
__device__ float g_q[(size_t)NB * NH * NS * HD];   // pre-scaled by 1/sqrt(d)
__device__ float g_k[(size_t)NB * NH * NS * HD];
__device__ float g_v[(size_t)NB * NH * NS * HD];
__device__ float g_qe[(size_t)NB * NH * NS * NR];  // q . emb_k[r], scale folded in

// ---------------------------------------------------------------------------
// Kernel 1: fused QKV projection.  C = hidden @ W + b, reshaped to [bh][s][d].
// blockIdx.z selects Q/K/V. Q is pre-scaled by 1/8.
// Tiles: BM=BN=64, BK=16, 256 threads, 4x4 micro-tile.
// ---------------------------------------------------------------------------
__global__ __launch_bounds__(256) void qkv_kernel(
    const float* __restrict__ hid,
    const float* __restrict__ Wq, const float* __restrict__ bq,
    const float* __restrict__ Wk, const float* __restrict__ bk,
    const float* __restrict__ Wv, const float* __restrict__ bv)
{
    const int bz = blockIdx.z;
    const float* W    = (bz == 0) ? Wq : (bz == 1) ? Wk : Wv;
    const float* bias = (bz == 0) ? bq : (bz == 1) ? bk : bv;
    float* out        = (bz == 0) ? g_q : (bz == 1) ? g_k : g_v;
    const float sc    = (bz == 0) ? 0.125f : 1.0f;   // 1/sqrt(64)

    __shared__ float As[64][17];   // [m][k], padded
    __shared__ float Bs[16][64];   // [k][n]

    const int tid = threadIdx.x;
    const int tx = tid & 15, ty = tid >> 4;
    const int m0 = blockIdx.y * 64, n0 = blockIdx.x * 64;

    float acc[4][4];
#pragma unroll
    for (int i = 0; i < 4; i++)
#pragma unroll
        for (int j = 0; j < 4; j++) acc[i][j] = 0.f;

    for (int k0 = 0; k0 < ND; k0 += 16) {
        {   // A tile 64x16
            int row = tid >> 2, c4 = (tid & 3) * 4;
            float4 a = *(const float4*)&hid[(size_t)(m0 + row) * ND + k0 + c4];
            As[row][c4 + 0] = a.x; As[row][c4 + 1] = a.y;
            As[row][c4 + 2] = a.z; As[row][c4 + 3] = a.w;
        }
        {   // B tile 16x64
            int row = tid >> 4, c4 = (tid & 15) * 4;
            *(float4*)&Bs[row][c4] = *(const float4*)&W[(size_t)(k0 + row) * ND + n0 + c4];
        }
        __syncthreads();
#pragma unroll
        for (int kk = 0; kk < 16; kk++) {
            float a[4];
#pragma unroll
            for (int i = 0; i < 4; i++) a[i] = As[ty + 16 * i][kk];
            float4 b4 = *(const float4*)&Bs[kk][tx * 4];
            float bb[4] = {b4.x, b4.y, b4.z, b4.w};
#pragma unroll
            for (int i = 0; i < 4; i++)
#pragma unroll
                for (int j = 0; j < 4; j++) acc[i][j] += a[i] * bb[j];
        }
        __syncthreads();
    }
#pragma unroll
    for (int i = 0; i < 4; i++) {
        int m = m0 + ty + 16 * i;          // m = b*S + s
        int b = m >> 11, s = m & (NS - 1);
#pragma unroll
        for (int j = 0; j < 4; j++) {
            int n = n0 + tx * 4 + j;       // n = h*64 + d
            int h = n >> 6, dd = n & 63;
            out[(((size_t)(b * NH + h) * NS) + s) * HD + dd] = (acc[i][j] + bias[n]) * sc;
        }
    }
}

// ---------------------------------------------------------------------------
// Kernel 2: qe[g][r] = sum_d g_q[g][d] * emb_k[r][d]   (g = (b*H+h)*S + s)
// 32 queries per CTA, emb_k staged in smem (stride-65 pad).
// ---------------------------------------------------------------------------
__global__ __launch_bounds__(128) void qe_kernel(const float* __restrict__ emb_k)
{
    __shared__ float eks[NR * 65];
    __shared__ float qs[32 * 65];
    const int tid = threadIdx.x;
    const size_t g0 = (size_t)blockIdx.x * 32;

    for (int i = tid; i < NR * HD; i += 128) {
        int r = i >> 6, d = i & 63;
        eks[r * 65 + d] = emb_k[i];
    }
    for (int i = tid; i < 32 * HD; i += 128) {
        int ql = i >> 6, d = i & 63;
        qs[ql * 65 + d] = g_q[(g0 + ql) * HD + d];
    }
    __syncthreads();

    for (int i = tid; i < 32 * NR; i += 128) {
        int ql = i / NR, r = i - ql * NR;
        float s = 0.f;
#pragma unroll
        for (int d = 0; d < HD; d++) s += qs[ql * 65 + d] * eks[r * 65 + d];
        g_qe[(g0 + ql) * NR + r] = s;
    }
}

// ---------------------------------------------------------------------------
// Kernel 3: flash attention with relative-position bias & value buckets.
// Grid (S/64, B*H), 128 threads. Thread tile: 4 queries (ty+16i) x 8 lanes.
// ---------------------------------------------------------------------------
__global__ __launch_bounds__(128) void attn_kernel(
    const float* __restrict__ mask, const float* __restrict__ emb_v,
    float* __restrict__ out)
{
    extern __shared__ float sm[];
    float* Qs   = sm;                    // [64][68]
    float* Ks   = Qs + 64 * 68;          // [64][68]
    float* Vs   = Ks + 64 * 68;          // [64][68]
    float* Ps   = Vs + 64 * 68;          // [64][68]
    float* pw   = Ps + 64 * 68;          // [64][129]
    float* mk   = pw + 64 * NR;          // [64]
    float* cvec = mk + 64;               // [64]

    const int tid = threadIdx.x;
    const int tx = tid & 7, ty = tid >> 3;          // ty in [0,16)
    const int qt = blockIdx.x, bh = blockIdx.y;
    const int b = bh >> 4, h = bh & 15;
    const size_t base = (size_t)bh * NS * HD;
    const int q0 = qt * 64;

    // load Q tile (padded stride 68)
    for (int i = tid; i < 64 * 16; i += 128) {
        int row = i >> 4, c4 = (i & 15) * 4;
        *(float4*)&Qs[row * 68 + c4] =
            *(const float4*)&g_q[base + (size_t)(q0 + row) * HD + c4];
    }
    for (int i = tid; i < 64 * NR; i += 128) pw[i] = 0.f;

    // constant-bucket biases for this thread's 4 query rows
    float qe0[4], qe128[4];
    const size_t qeb = ((size_t)bh * NS + q0) * NR;
#pragma unroll
    for (int i = 0; i < 4; i++) {
        int q = ty + 16 * i;
        qe0[i]   = g_qe[qeb + (size_t)q * NR + 0];
        qe128[i] = g_qe[qeb + (size_t)q * NR + 128];
    }

    float m_i[4], l_i[4], acc[4][8];
#pragma unroll
    for (int i = 0; i < 4; i++) {
        m_i[i] = -1e30f; l_i[i] = 0.f;
#pragma unroll
        for (int j = 0; j < 8; j++) acc[i][j] = 0.f;
    }
    __syncthreads();

    for (int kt = 0; kt < NS / 64; kt++) {
        const int k0 = kt * 64;
        for (int i = tid; i < 64 * 16; i += 128) {
            int row = i >> 4, c4 = (i & 15) * 4;
            *(float4*)&Ks[row * 68 + c4] =
                *(const float4*)&g_k[base + (size_t)(k0 + row) * HD + c4];
            *(float4*)&Vs[row * 68 + c4] =
                *(const float4*)&g_v[base + (size_t)(k0 + row) * HD + c4];
        }
        if (tid < 64) mk[tid] = mask[b * NS + k0 + tid];
        __syncthreads();

        // S = Q K^T
        float s[4][8];
#pragma unroll
        for (int i = 0; i < 4; i++)
#pragma unroll
            for (int j = 0; j < 8; j++) s[i][j] = 0.f;
#pragma unroll 8
        for (int dd = 0; dd < HD; dd++) {
            float aq[4], bk[8];
#pragma unroll
            for (int i = 0; i < 4; i++) aq[i] = Qs[(ty + 16 * i) * 68 + dd];
#pragma unroll
            for (int j = 0; j < 8; j++) bk[j] = Ks[(tx + 8 * j) * 68 + dd];
#pragma unroll
            for (int i = 0; i < 4; i++)
#pragma unroll
                for (int j = 0; j < 8; j++) s[i][j] += aq[i] * bk[j];
        }

        // relative-position bias + mask
        const int dt = qt - kt;
        if (dt >= 2) {
#pragma unroll
            for (int i = 0; i < 4; i++)
#pragma unroll
                for (int j = 0; j < 8; j++) s[i][j] += qe128[i] + mk[tx + 8 * j];
        } else if (dt <= -2) {
#pragma unroll
            for (int i = 0; i < 4; i++)
#pragma unroll
                for (int j = 0; j < 8; j++) s[i][j] += qe0[i] + mk[tx + 8 * j];
        } else {
#pragma unroll
            for (int i = 0; i < 4; i++) {
                int qg = q0 + ty + 16 * i;
                const float* qer = &g_qe[((size_t)bh * NS + qg) * NR];
#pragma unroll
                for (int j = 0; j < 8; j++) {
                    int kg = k0 + tx + 8 * j;
                    int rp = qg - kg;
                    rp = rp < -64 ? -64 : (rp > 64 ? 64 : rp);
                    s[i][j] += __ldg(&qer[rp + 64]) + mk[tx + 8 * j];
                }
            }
        }

        // streaming softmax
        float c[4], rstile[4];
#pragma unroll
        for (int i = 0; i < 4; i++) {
            float rmax = s[i][0];
#pragma unroll
            for (int j = 1; j < 8; j++) rmax = fmaxf(rmax, s[i][j]);
#pragma unroll
            for (int o = 1; o < 8; o <<= 1)
                rmax = fmaxf(rmax, __shfl_xor_sync(0xffffffffu, rmax, o));
            float mn = fmaxf(m_i[i], rmax);
            c[i] = __expf(m_i[i] - mn);
            m_i[i] = mn;
            float rs = 0.f;
#pragma unroll
            for (int j = 0; j < 8; j++) { s[i][j] = __expf(s[i][j] - mn); rs += s[i][j]; }
#pragma unroll
            for (int o = 1; o < 8; o <<= 1) rs += __shfl_xor_sync(0xffffffffu, rs, o);
            l_i[i] = l_i[i] * c[i] + rs;
            rstile[i] = rs;
#pragma unroll
            for (int j = 0; j < 8; j++) acc[i][j] *= c[i];
        }

        // stage P + correction vector
#pragma unroll
        for (int i = 0; i < 4; i++)
#pragma unroll
            for (int j = 0; j < 8; j++) Ps[(ty + 16 * i) * 68 + tx + 8 * j] = s[i][j];
        if (tx == 0) {
#pragma unroll
            for (int i = 0; i < 4; i++) cvec[ty + 16 * i] = c[i];
        }
        __syncthreads();

        // rescale pw by per-query correction (skip when max unchanged)
        {
            int q = tid >> 1;
            float cc = cvec[q];
            if (cc != 1.0f) {
                int r0 = (tid & 1) * 65;
                int r1 = (tid & 1) ? NR : 65;
                for (int r = r0; r < r1; r++) pw[q * NR + r] *= cc;
            }
        }
        __syncthreads();

        // bucket-probability accumulation
        if (dt >= 2) {
            if (tx == 0)
#pragma unroll
                for (int i = 0; i < 4; i++) pw[(ty + 16 * i) * NR + 128] += rstile[i];
        } else if (dt <= -2) {
            if (tx == 0)
#pragma unroll
                for (int i = 0; i < 4; i++) pw[(ty + 16 * i) * NR + 0] += rstile[i];
        } else {
#pragma unroll
            for (int i = 0; i < 4; i++) {
                int qg = q0 + ty + 16 * i;
#pragma unroll
                for (int j = 0; j < 8; j++) {
                    int kg = k0 + tx + 8 * j;
                    int rp = qg - kg;
                    rp = rp < -64 ? -64 : (rp > 64 ? 64 : rp);
                    atomicAdd(&pw[(ty + 16 * i) * NR + rp + 64], s[i][j]);
                }
            }
        }

        // O += P V
#pragma unroll 4
        for (int k = 0; k < 64; k++) {
            float pk[4], vv[8];
#pragma unroll
            for (int i = 0; i < 4; i++) pk[i] = Ps[(ty + 16 * i) * 68 + k];
#pragma unroll
            for (int j = 0; j < 8; j++) vv[j] = Vs[k * 68 + tx + 8 * j];
#pragma unroll
            for (int i = 0; i < 4; i++)
#pragma unroll
                for (int j = 0; j < 8; j++) acc[i][j] += pk[i] * vv[j];
        }
        __syncthreads();
    }

    // epilogue: ctx_rel = pw @ emb_v   (emb_v staged over dead Qs/Ks space)
    float* evs = Qs;   // needs 129*64 = 8256 floats, Qs+Ks span 8704
    for (int i = tid; i < NR * HD; i += 128) evs[i] = emb_v[i];
    __syncthreads();

    float rel[4][8];
#pragma unroll
    for (int i = 0; i < 4; i++)
#pragma unroll
        for (int j = 0; j < 8; j++) rel[i][j] = 0.f;
#pragma unroll 4
    for (int r = 0; r < NR; r++) {
        float pr[4], ev[8];
#pragma unroll
        for (int i = 0; i < 4; i++) pr[i] = pw[(ty + 16 * i) * NR + r];
#pragma unroll
        for (int j = 0; j < 8; j++) ev[j] = evs[r * HD + tx + 8 * j];
#pragma unroll
        for (int i = 0; i < 4; i++)
#pragma unroll
            for (int j = 0; j < 8; j++) rel[i][j] += pr[i] * ev[j];
    }

#pragma unroll
    for (int i = 0; i < 4; i++) {
        int qg = q0 + ty + 16 * i;
        float inv = 1.0f / l_i[i];
#pragma unroll
        for (int j = 0; j < 8; j++)
            out[((size_t)(b * NS + qg)) * ND + h * HD + tx + 8 * j] =
                (acc[i][j] + rel[i][j]) * inv;
    }
}

// ---------------------------------------------------------------------------
extern "C" void kernel_launch(void* const* d_in, const int* in_sizes, int n_in,
                              void* d_out, int out_size)
{
    const float* hid   = (const float*)d_in[0];
    const float* mask  = (const float*)d_in[1];
    const float* Wq    = (const float*)d_in[2];
    const float* bq    = (const float*)d_in[3];
    const float* Wk    = (const float*)d_in[4];
    const float* bk    = (const float*)d_in[5];
    const float* Wv    = (const float*)d_in[6];
    const float* bv    = (const float*)d_in[7];
    const float* emb_k = (const float*)d_in[8];
    const float* emb_v = (const float*)d_in[9];
    float* out = (float*)d_out;

    dim3 g1(ND / 64, (NB * NS) / 64, 3);
    qkv_kernel<<<g1, 256>>>(hid, Wq, bq, Wk, bk, Wv, bv);

    qe_kernel<<<(NB * NH * NS) / 32, 128>>>(emb_k);

    size_t smem = (size_t)(4 * 64 * 68 + 64 * NR + 128) * sizeof(float);
    cudaFuncSetAttribute(attn_kernel, cudaFuncAttributeMaxDynamicSharedMemorySize,
                         (int)smem);
    attn_kernel<<<dim3(NS / 64, NB * NH), 128, smem>>>(mask, emb_v, out);
}

// round 5
// speedup vs baseline: 1.0411x; 1.0411x over previous
#include <cuda_runtime.h>

#define NB 2
#define NS 2048
#define ND 1024
#define NH 16
#define HD 64
#define NR 129   // 2*64+1 relative buckets

// scratch (allocation-free rule: device globals)
__device__ float g_q[(size_t)NB * NH * NS * HD];   // pre-scaled by 1/sqrt(d)
__device__ float g_k[(size_t)NB * NH * NS * HD];
__device__ float g_v[(size_t)NB * NH * NS * HD];
__device__ float g_qe[(size_t)NB * NH * NS * NR];  // q . emb_k[r], scale folded in

// ---------------------------------------------------------------------------
// Kernel 1: fused QKV projection.  C = hidden @ W + b -> [bh][s][d].
// 128x128 block tile, BK=8, 256 threads, 8x8 microtile, reg-prefetch.
// ---------------------------------------------------------------------------
__global__ __launch_bounds__(256) void qkv_kernel(
    const float* __restrict__ hid,
    const float* __restrict__ Wq, const float* __restrict__ bq,
    const float* __restrict__ Wk, const float* __restrict__ bk,
    const float* __restrict__ Wv, const float* __restrict__ bv)
{
    const int bz = blockIdx.z;
    const float* W    = (bz == 0) ? Wq : (bz == 1) ? Wk : Wv;
    const float* bias = (bz == 0) ? bq : (bz == 1) ? bk : bv;
    float* out        = (bz == 0) ? g_q : (bz == 1) ? g_k : g_v;
    const float sc    = (bz == 0) ? 0.125f : 1.0f;   // 1/sqrt(64)

    __shared__ float As[8][132];   // [k][m]
    __shared__ float Bs[8][132];   // [k][n]

    const int tid = threadIdx.x;
    const int tx = tid & 15, ty = tid >> 4;          // 16x16 thread grid
    const int m0 = blockIdx.y * 128, n0 = blockIdx.x * 128;

    const int arow = tid >> 1;            // 0..127 (m)
    const int acol = (tid & 1) * 4;       // k offset 0/4
    const int brow = tid >> 5;            // 0..7   (k)
    const int bcol = (tid & 31) * 4;      // n

    float acc[8][8];
#pragma unroll
    for (int i = 0; i < 8; i++)
#pragma unroll
        for (int j = 0; j < 8; j++) acc[i][j] = 0.f;

    // preload tile 0
    {
        float4 a = *(const float4*)&hid[(size_t)(m0 + arow) * ND + acol];
        float4 b = *(const float4*)&W[(size_t)brow * ND + n0 + bcol];
        As[acol + 0][arow] = a.x; As[acol + 1][arow] = a.y;
        As[acol + 2][arow] = a.z; As[acol + 3][arow] = a.w;
        *(float4*)&Bs[brow][bcol] = b;
    }
    __syncthreads();

    for (int k0 = 0; k0 < ND; k0 += 8) {
        const bool more = (k0 + 8) < ND;
        float4 a_nf, b_nf;
        if (more) {
            a_nf = *(const float4*)&hid[(size_t)(m0 + arow) * ND + k0 + 8 + acol];
            b_nf = *(const float4*)&W[(size_t)(k0 + 8 + brow) * ND + n0 + bcol];
        }
#pragma unroll
        for (int kk = 0; kk < 8; kk++) {
            float4 a0 = *(const float4*)&As[kk][ty * 8];
            float4 a1 = *(const float4*)&As[kk][ty * 8 + 4];
            float4 b0 = *(const float4*)&Bs[kk][tx * 8];
            float4 b1 = *(const float4*)&Bs[kk][tx * 8 + 4];
            float av[8] = {a0.x, a0.y, a0.z, a0.w, a1.x, a1.y, a1.z, a1.w};
            float bv2[8] = {b0.x, b0.y, b0.z, b0.w, b1.x, b1.y, b1.z, b1.w};
#pragma unroll
            for (int i = 0; i < 8; i++)
#pragma unroll
                for (int j = 0; j < 8; j++) acc[i][j] += av[i] * bv2[j];
        }
        __syncthreads();
        if (more) {
            As[acol + 0][arow] = a_nf.x; As[acol + 1][arow] = a_nf.y;
            As[acol + 2][arow] = a_nf.z; As[acol + 3][arow] = a_nf.w;
            *(float4*)&Bs[brow][bcol] = b_nf;
            __syncthreads();
        }
    }

#pragma unroll
    for (int i = 0; i < 8; i++) {
        int m = m0 + ty * 8 + i;           // m = b*S + s
        int b = m >> 11, s = m & (NS - 1);
#pragma unroll
        for (int jj = 0; jj < 2; jj++) {
            int n = n0 + tx * 8 + jj * 4;  // n = h*64 + d, 4 consecutive
            int h = n >> 6, dd = n & 63;
            float4 o;
            o.x = (acc[i][jj * 4 + 0] + bias[n + 0]) * sc;
            o.y = (acc[i][jj * 4 + 1] + bias[n + 1]) * sc;
            o.z = (acc[i][jj * 4 + 2] + bias[n + 2]) * sc;
            o.w = (acc[i][jj * 4 + 3] + bias[n + 3]) * sc;
            *(float4*)&out[(((size_t)(b * NH + h) * NS) + s) * HD + dd] = o;
        }
    }
}

// ---------------------------------------------------------------------------
// Kernel 2: qe[g][r] = sum_d g_q[g][d] * emb_k[r][d]
// ---------------------------------------------------------------------------
__global__ __launch_bounds__(128) void qe_kernel(const float* __restrict__ emb_k)
{
    __shared__ float eks[NR * 65];
    __shared__ float qs[32 * 65];
    const int tid = threadIdx.x;
    const size_t g0 = (size_t)blockIdx.x * 32;

    for (int i = tid; i < NR * HD; i += 128) {
        int r = i >> 6, d = i & 63;
        eks[r * 65 + d] = emb_k[i];
    }
    for (int i = tid; i < 32 * HD; i += 128) {
        int ql = i >> 6, d = i & 63;
        qs[ql * 65 + d] = g_q[(g0 + ql) * HD + d];
    }
    __syncthreads();

    for (int i = tid; i < 32 * NR; i += 128) {
        int ql = i / NR, r = i - ql * NR;
        float s = 0.f;
#pragma unroll
        for (int d = 0; d < HD; d++) s += qs[ql * 65 + d] * eks[r * 65 + d];
        g_qe[(g0 + ql) * NR + r] = s;
    }
}

// ---------------------------------------------------------------------------
// Kernel 3: flash attention w/ relative bias & value buckets.
// 128 threads, 64x64 tiles. Thread (tx=tid&7, ty=tid>>3):
//   queries q = ty*4+i (4 consecutive), QK keys = tx+8j, PV/out cols = tx*8+j.
// ---------------------------------------------------------------------------
__global__ __launch_bounds__(128) void attn_kernel(
    const float* __restrict__ mask, const float* __restrict__ emb_v,
    float* __restrict__ out)
{
    extern __shared__ float sm[];
    float* Qs   = sm;                    // [64][68] natural [row][d]
    float* Ks   = Qs + 64 * 68;          // [64][68]
    float* Vs   = Ks + 64 * 68;          // [64][68]
    float* Pt   = Vs + 64 * 68;          // [key][q] 64x68
    float* pwt  = Pt + 64 * 68;          // [129][68]  (r-major, q minor)
    float* mk   = pwt + NR * 68;         // [64]
    float* cvec = mk + 64;               // [64]

    const int tid = threadIdx.x;
    const int tx = tid & 7, ty = tid >> 3;          // ty in [0,16)
    const int qt = blockIdx.x, bh = blockIdx.y;
    const int b = bh >> 4, h = bh & 15;
    const size_t base = (size_t)bh * NS * HD;
    const int q0 = qt * 64;

    for (int i = tid; i < 64 * 16; i += 128) {
        int row = i >> 4, c4 = (i & 15) * 4;
        *(float4*)&Qs[row * 68 + c4] =
            *(const float4*)&g_q[base + (size_t)(q0 + row) * HD + c4];
    }
    for (int i = tid; i < NR * 68; i += 128) pwt[i] = 0.f;

    float qe0[4], qe128[4];
    const size_t qeb = ((size_t)bh * NS + q0) * NR;
#pragma unroll
    for (int i = 0; i < 4; i++) {
        int q = ty * 4 + i;
        qe0[i]   = g_qe[qeb + (size_t)q * NR + 0];
        qe128[i] = g_qe[qeb + (size_t)q * NR + 128];
    }

    float m_i[4], l_i[4], acc[4][8];
#pragma unroll
    for (int i = 0; i < 4; i++) {
        m_i[i] = -1e30f; l_i[i] = 0.f;
#pragma unroll
        for (int j = 0; j < 8; j++) acc[i][j] = 0.f;
    }
    __syncthreads();

    for (int kt = 0; kt < NS / 64; kt++) {
        const int k0 = kt * 64;
        for (int i = tid; i < 64 * 16; i += 128) {
            int row = i >> 4, c4 = (i & 15) * 4;
            *(float4*)&Ks[row * 68 + c4] =
                *(const float4*)&g_k[base + (size_t)(k0 + row) * HD + c4];
            *(float4*)&Vs[row * 68 + c4] =
                *(const float4*)&g_v[base + (size_t)(k0 + row) * HD + c4];
        }
        if (tid < 64) mk[tid] = mask[b * NS + k0 + tid];
        __syncthreads();

        // ---- S = Q K^T  (dot-4 chunks, all LDS.128) ----
        float s[4][8];
#pragma unroll
        for (int i = 0; i < 4; i++)
#pragma unroll
            for (int j = 0; j < 8; j++) s[i][j] = 0.f;
#pragma unroll 4
        for (int c4 = 0; c4 < HD; c4 += 4) {
            float4 aq[4], bk[8];
#pragma unroll
            for (int i = 0; i < 4; i++)
                aq[i] = *(const float4*)&Qs[(ty * 4 + i) * 68 + c4];
#pragma unroll
            for (int j = 0; j < 8; j++)
                bk[j] = *(const float4*)&Ks[(tx + 8 * j) * 68 + c4];
#pragma unroll
            for (int i = 0; i < 4; i++)
#pragma unroll
                for (int j = 0; j < 8; j++) {
                    s[i][j] += aq[i].x * bk[j].x;
                    s[i][j] += aq[i].y * bk[j].y;
                    s[i][j] += aq[i].z * bk[j].z;
                    s[i][j] += aq[i].w * bk[j].w;
                }
        }

        // ---- relative bias + mask ----
        const int dt = qt - kt;
        if (dt >= 2) {
#pragma unroll
            for (int i = 0; i < 4; i++)
#pragma unroll
                for (int j = 0; j < 8; j++) s[i][j] += qe128[i] + mk[tx + 8 * j];
        } else if (dt <= -2) {
#pragma unroll
            for (int i = 0; i < 4; i++)
#pragma unroll
                for (int j = 0; j < 8; j++) s[i][j] += qe0[i] + mk[tx + 8 * j];
        } else {
#pragma unroll
            for (int i = 0; i < 4; i++) {
                int qg = q0 + ty * 4 + i;
                const float* qer = &g_qe[((size_t)bh * NS + qg) * NR];
#pragma unroll
                for (int j = 0; j < 8; j++) {
                    int kg = k0 + tx + 8 * j;
                    int rp = qg - kg;
                    rp = rp < -64 ? -64 : (rp > 64 ? 64 : rp);
                    s[i][j] += __ldg(&qer[rp + 64]) + mk[tx + 8 * j];
                }
            }
        }

        // ---- streaming softmax ----
        float c[4], rstile[4];
#pragma unroll
        for (int i = 0; i < 4; i++) {
            float rmax = s[i][0];
#pragma unroll
            for (int j = 1; j < 8; j++) rmax = fmaxf(rmax, s[i][j]);
#pragma unroll
            for (int o = 1; o < 8; o <<= 1)
                rmax = fmaxf(rmax, __shfl_xor_sync(0xffffffffu, rmax, o));
            float mn = fmaxf(m_i[i], rmax);
            c[i] = __expf(m_i[i] - mn);
            m_i[i] = mn;
            float rs = 0.f;
#pragma unroll
            for (int j = 0; j < 8; j++) { s[i][j] = __expf(s[i][j] - mn); rs += s[i][j]; }
#pragma unroll
            for (int o = 1; o < 8; o <<= 1) rs += __shfl_xor_sync(0xffffffffu, rs, o);
            l_i[i] = l_i[i] * c[i] + rs;
            rstile[i] = rs;
#pragma unroll
            for (int j = 0; j < 8; j++) acc[i][j] *= c[i];
        }

        // stage P transposed [key][q] + correction vector
#pragma unroll
        for (int i = 0; i < 4; i++)
#pragma unroll
            for (int j = 0; j < 8; j++)
                Pt[(tx + 8 * j) * 68 + ty * 4 + i] = s[i][j];
        if (tx == 0) {
#pragma unroll
            for (int i = 0; i < 4; i++) cvec[ty * 4 + i] = c[i];
        }

        int anyc = (c[0] != 1.f) | (c[1] != 1.f) | (c[2] != 1.f) | (c[3] != 1.f);
        int need = __syncthreads_or(anyc);   // barrier: orders Pt/cvec too
        if (need) {
            for (int i = tid; i < NR * 64; i += 128) {
                int r = i >> 6, q = i & 63;
                pwt[r * 68 + q] *= cvec[q];
            }
            __syncthreads();
        }

        // ---- bucket-probability accumulation (writer-unique, plain RMW) ----
        if (dt >= 2) {
            if (tx == 0)
#pragma unroll
                for (int i = 0; i < 4; i++) pwt[128 * 68 + ty * 4 + i] += rstile[i];
        } else if (dt <= -2) {
            if (tx == 0)
#pragma unroll
                for (int i = 0; i < 4; i++) pwt[0 * 68 + ty * 4 + i] += rstile[i];
        } else if (dt == -1) {
            // rp in [-127,-1]; rp<=-64 collapses to bucket 0: row-reduce it
#pragma unroll
            for (int i = 0; i < 4; i++) {
                int qg = q0 + ty * 4 + i;
                float csum = 0.f;
#pragma unroll
                for (int j = 0; j < 8; j++) {
                    int kg = k0 + tx + 8 * j;
                    int rp = qg - kg;
                    if (rp <= -64) csum += s[i][j];
                    else pwt[(rp + 64) * 68 + ty * 4 + i] += s[i][j];
                }
#pragma unroll
                for (int o = 1; o < 8; o <<= 1)
                    csum += __shfl_xor_sync(0xffffffffu, csum, o);
                if (tx == 0) pwt[0 * 68 + ty * 4 + i] += csum;
            }
        } else if (dt == 1) {
            // rp in [1,127]; rp>=64 collapses to bucket 128: row-reduce it
#pragma unroll
            for (int i = 0; i < 4; i++) {
                int qg = q0 + ty * 4 + i;
                float csum = 0.f;
#pragma unroll
                for (int j = 0; j < 8; j++) {
                    int kg = k0 + tx + 8 * j;
                    int rp = qg - kg;
                    if (rp >= 64) csum += s[i][j];
                    else pwt[(rp + 64) * 68 + ty * 4 + i] += s[i][j];
                }
#pragma unroll
                for (int o = 1; o < 8; o <<= 1)
                    csum += __shfl_xor_sync(0xffffffffu, csum, o);
                if (tx == 0) pwt[128 * 68 + ty * 4 + i] += csum;
            }
        } else {
            // dt==0: rp in [-63,63], no clamping, buckets unique per (q,key)
#pragma unroll
            for (int i = 0; i < 4; i++) {
                int qg = q0 + ty * 4 + i;
#pragma unroll
                for (int j = 0; j < 8; j++) {
                    int kg = k0 + tx + 8 * j;
                    int rp = qg - kg;
                    pwt[(rp + 64) * 68 + ty * 4 + i] += s[i][j];
                }
            }
        }

        // ---- O += P V ----
#pragma unroll 4
        for (int k = 0; k < 64; k++) {
            float4 p4 = *(const float4*)&Pt[k * 68 + ty * 4];
            float4 v0 = *(const float4*)&Vs[k * 68 + tx * 8];
            float4 v1 = *(const float4*)&Vs[k * 68 + tx * 8 + 4];
            float pk[4] = {p4.x, p4.y, p4.z, p4.w};
            float vv[8] = {v0.x, v0.y, v0.z, v0.w, v1.x, v1.y, v1.z, v1.w};
#pragma unroll
            for (int i = 0; i < 4; i++)
#pragma unroll
                for (int j = 0; j < 8; j++) acc[i][j] += pk[i] * vv[j];
        }
        __syncthreads();
    }

    // ---- epilogue: ctx_rel = pw @ emb_v (emb_v staged over dead Qs/Ks) ----
    float* evs = Qs;   // 129*64 = 8256 floats <= 8704 (Qs+Ks)
    for (int i = tid; i < NR * HD; i += 128) evs[i] = emb_v[i];
    __syncthreads();

    float rel[4][8];
#pragma unroll
    for (int i = 0; i < 4; i++)
#pragma unroll
        for (int j = 0; j < 8; j++) rel[i][j] = 0.f;
#pragma unroll 4
    for (int r = 0; r < NR; r++) {
        float4 p4 = *(const float4*)&pwt[r * 68 + ty * 4];
        float4 e0 = *(const float4*)&evs[r * HD + tx * 8];
        float4 e1 = *(const float4*)&evs[r * HD + tx * 8 + 4];
        float pr[4] = {p4.x, p4.y, p4.z, p4.w};
        float ev[8] = {e0.x, e0.y, e0.z, e0.w, e1.x, e1.y, e1.z, e1.w};
#pragma unroll
        for (int i = 0; i < 4; i++)
#pragma unroll
            for (int j = 0; j < 8; j++) rel[i][j] += pr[i] * ev[j];
    }

#pragma unroll
    for (int i = 0; i < 4; i++) {
        int qg = q0 + ty * 4 + i;
        float inv = 1.0f / l_i[i];
        float* op = &out[((size_t)(b * NS + qg)) * ND + h * HD + tx * 8];
        float4 o0, o1;
        o0.x = (acc[i][0] + rel[i][0]) * inv;
        o0.y = (acc[i][1] + rel[i][1]) * inv;
        o0.z = (acc[i][2] + rel[i][2]) * inv;
        o0.w = (acc[i][3] + rel[i][3]) * inv;
        o1.x = (acc[i][4] + rel[i][4]) * inv;
        o1.y = (acc[i][5] + rel[i][5]) * inv;
        o1.z = (acc[i][6] + rel[i][6]) * inv;
        o1.w = (acc[i][7] + rel[i][7]) * inv;
        *(float4*)&op[0] = o0;
        *(float4*)&op[4] = o1;
    }
}

// ---------------------------------------------------------------------------
extern "C" void kernel_launch(void* const* d_in, const int* in_sizes, int n_in,
                              void* d_out, int out_size)
{
    const float* hid   = (const float*)d_in[0];
    const float* mask  = (const float*)d_in[1];
    const float* Wq    = (const float*)d_in[2];
    const float* bq    = (const float*)d_in[3];
    const float* Wk    = (const float*)d_in[4];
    const float* bk    = (const float*)d_in[5];
    const float* Wv    = (const float*)d_in[6];
    const float* bv    = (const float*)d_in[7];
    const float* emb_k = (const float*)d_in[8];
    const float* emb_v = (const float*)d_in[9];
    float* out = (float*)d_out;

    dim3 g1(ND / 128, (NB * NS) / 128, 3);
    qkv_kernel<<<g1, 256>>>(hid, Wq, bq, Wk, bk, Wv, bv);

    qe_kernel<<<(NB * NH * NS) / 32, 128>>>(emb_k);

    size_t smem = (size_t)(4 * 64 * 68 + NR * 68 + 128) * sizeof(float);
    cudaFuncSetAttribute(attn_kernel, cudaFuncAttributeMaxDynamicSharedMemorySize,
                         (int)smem);
    attn_kernel<<<dim3(NS / 64, NB * NH), 128, smem>>>(mask, emb_v, out);
}

// round 7
// speedup vs baseline: 1.2126x; 1.1648x over previous
#include <cuda_runtime.h>

#define NB 2
#define NS 2048
#define ND 1024
#define NH 16
#define HD 64
#define NR 129   // 2*64+1 relative buckets

typedef unsigned long long u64;

__device__ __forceinline__ void fma2(u64& d, u64 a, u64 b) {
    asm("fma.rn.f32x2 %0, %1, %2, %0;" : "+l"(d) : "l"(a), "l"(b));
}
__device__ __forceinline__ void mul2(u64& d, u64 a) {
    asm("mul.rn.f32x2 %0, %0, %1;" : "+l"(d) : "l"(a));
}
__device__ __forceinline__ u64 dup2(float x) {
    u64 o; unsigned r = __float_as_uint(x);
    asm("mov.b64 %0, {%1, %1};" : "=l"(o) : "r"(r));
    return o;
}
__device__ __forceinline__ float2 unpack2(u64 v) {
    unsigned lo, hi;
    asm("mov.b64 {%0, %1}, %2;" : "=r"(lo), "=r"(hi) : "l"(v));
    return make_float2(__uint_as_float(lo), __uint_as_float(hi));
}

// scratch (allocation-free rule: device globals)
__device__ float g_q[(size_t)NB * NH * NS * HD];   // pre-scaled by 1/sqrt(d)
__device__ float g_k[(size_t)NB * NH * NS * HD];
__device__ float g_v[(size_t)NB * NH * NS * HD];
__device__ float g_qe[(size_t)NB * NH * NS * NR];  // q . emb_k[r], scale folded in

// ---------------------------------------------------------------------------
// Kernel 1: fused QKV projection. 128x128x8 tile, 256 thr, 8x8 microtile,
// FFMA2 packed along N.
// ---------------------------------------------------------------------------
__global__ __launch_bounds__(256) void qkv_kernel(
    const float* __restrict__ hid,
    const float* __restrict__ Wq, const float* __restrict__ bq,
    const float* __restrict__ Wk, const float* __restrict__ bk,
    const float* __restrict__ Wv, const float* __restrict__ bv)
{
    const int bz = blockIdx.z;
    const float* W    = (bz == 0) ? Wq : (bz == 1) ? Wk : Wv;
    const float* bias = (bz == 0) ? bq : (bz == 1) ? bk : bv;
    float* out        = (bz == 0) ? g_q : (bz == 1) ? g_k : g_v;
    const float sc    = (bz == 0) ? 0.125f : 1.0f;   // 1/sqrt(64)

    __shared__ float As[8][132];   // [k][m]
    __shared__ float Bs[8][132];   // [k][n]

    const int tid = threadIdx.x;
    const int tx = tid & 15, ty = tid >> 4;
    const int m0 = blockIdx.y * 128, n0 = blockIdx.x * 128;

    const int arow = tid >> 1;
    const int acol = (tid & 1) * 4;
    const int brow = tid >> 5;
    const int bcol = (tid & 31) * 4;

    u64 acc2[8][4];
#pragma unroll
    for (int i = 0; i < 8; i++)
#pragma unroll
        for (int j = 0; j < 4; j++) acc2[i][j] = 0ULL;

    {   // preload tile 0
        float4 a = *(const float4*)&hid[(size_t)(m0 + arow) * ND + acol];
        float4 b = *(const float4*)&W[(size_t)brow * ND + n0 + bcol];
        As[acol + 0][arow] = a.x; As[acol + 1][arow] = a.y;
        As[acol + 2][arow] = a.z; As[acol + 3][arow] = a.w;
        *(float4*)&Bs[brow][bcol] = b;
    }
    __syncthreads();

    for (int k0 = 0; k0 < ND; k0 += 8) {
        const bool more = (k0 + 8) < ND;
        float4 a_nf, b_nf;
        if (more) {
            a_nf = *(const float4*)&hid[(size_t)(m0 + arow) * ND + k0 + 8 + acol];
            b_nf = *(const float4*)&W[(size_t)(k0 + 8 + brow) * ND + n0 + bcol];
        }
#pragma unroll
        for (int kk = 0; kk < 8; kk++) {
            float4 a0 = *(const float4*)&As[kk][ty * 8];
            float4 a1 = *(const float4*)&As[kk][ty * 8 + 4];
            ulonglong2 bl0 = *(const ulonglong2*)&Bs[kk][tx * 8];
            ulonglong2 bl1 = *(const ulonglong2*)&Bs[kk][tx * 8 + 4];
            u64 bvp[4] = {bl0.x, bl0.y, bl1.x, bl1.y};
            float av[8] = {a0.x, a0.y, a0.z, a0.w, a1.x, a1.y, a1.z, a1.w};
#pragma unroll
            for (int i = 0; i < 8; i++) {
                u64 ad = dup2(av[i]);
#pragma unroll
                for (int j = 0; j < 4; j++) fma2(acc2[i][j], ad, bvp[j]);
            }
        }
        __syncthreads();
        if (more) {
            As[acol + 0][arow] = a_nf.x; As[acol + 1][arow] = a_nf.y;
            As[acol + 2][arow] = a_nf.z; As[acol + 3][arow] = a_nf.w;
            *(float4*)&Bs[brow][bcol] = b_nf;
            __syncthreads();
        }
    }

#pragma unroll
    for (int i = 0; i < 8; i++) {
        int m = m0 + ty * 8 + i;           // m = b*S + s
        int b = m >> 11, s = m & (NS - 1);
#pragma unroll
        for (int jj = 0; jj < 2; jj++) {
            int n = n0 + tx * 8 + jj * 4;  // n = h*64 + d
            int h = n >> 6, dd = n & 63;
            float2 p0 = unpack2(acc2[i][jj * 2 + 0]);
            float2 p1 = unpack2(acc2[i][jj * 2 + 1]);
            float4 o;
            o.x = (p0.x + bias[n + 0]) * sc;
            o.y = (p0.y + bias[n + 1]) * sc;
            o.z = (p1.x + bias[n + 2]) * sc;
            o.w = (p1.y + bias[n + 3]) * sc;
            *(float4*)&out[(((size_t)(b * NH + h) * NS) + s) * HD + dd] = o;
        }
    }
}

// ---------------------------------------------------------------------------
// Kernel 2: qe[g][r] = sum_d g_q[g][d] * emb_k[r][d]
// ---------------------------------------------------------------------------
__global__ __launch_bounds__(128) void qe_kernel(const float* __restrict__ emb_k)
{
    __shared__ float eks[NR * 65];
    __shared__ float qs[32 * 65];
    const int tid = threadIdx.x;
    const size_t g0 = (size_t)blockIdx.x * 32;

    for (int i = tid; i < NR * HD; i += 128) {
        int r = i >> 6, d = i & 63;
        eks[r * 65 + d] = emb_k[i];
    }
    for (int i = tid; i < 32 * HD; i += 128) {
        int ql = i >> 6, d = i & 63;
        qs[ql * 65 + d] = g_q[(g0 + ql) * HD + d];
    }
    __syncthreads();

    for (int i = tid; i < 32 * NR; i += 128) {
        int ql = i / NR, r = i - ql * NR;
        float s = 0.f;
#pragma unroll
        for (int d = 0; d < HD; d++) s += qs[ql * 65 + d] * eks[r * 65 + d];
        g_qe[(g0 + ql) * NR + r] = s;
    }
}

// ---------------------------------------------------------------------------
// Kernel 3: flash attention w/ relative bias & value buckets. FFMA2 packed.
// pw accumulated in ABSOLUTE exp units (no per-tile rescale / extra barrier).
// ---------------------------------------------------------------------------
__global__ __launch_bounds__(128) void attn_kernel(
    const float* __restrict__ mask, const float* __restrict__ emb_v,
    float* __restrict__ out)
{
    extern __shared__ float sm[];
    float* Qs   = sm;                    // [64][68]
    float* Ks   = Qs + 64 * 68;          // [64][68]
    float* Vs   = Ks + 64 * 68;          // [64][68]
    float* Pt   = Vs + 64 * 68;          // [key][q] 64x68
    float* pwt  = Pt + 64 * 68;          // [129][68]  (r-major, q minor)
    float* mk   = pwt + NR * 68;         // [64]

    const int tid = threadIdx.x;
    const int tx = tid & 7, ty = tid >> 3;          // ty in [0,16)
    const int qt = blockIdx.x, bh = blockIdx.y;
    const int b = bh >> 4, h = bh & 15;
    const size_t base = (size_t)bh * NS * HD;
    const int q0 = qt * 64;

    for (int i = tid; i < 64 * 16; i += 128) {
        int row = i >> 4, c4 = (i & 15) * 4;
        *(float4*)&Qs[row * 68 + c4] =
            *(const float4*)&g_q[base + (size_t)(q0 + row) * HD + c4];
    }
    for (int i = tid; i < NR * 68; i += 128) pwt[i] = 0.f;

    float qe0[4], qe128[4];
    const size_t qeb = ((size_t)bh * NS + q0) * NR;
#pragma unroll
    for (int i = 0; i < 4; i++) {
        int q = ty * 4 + i;
        qe0[i]   = g_qe[qeb + (size_t)q * NR + 0];
        qe128[i] = g_qe[qeb + (size_t)q * NR + 128];
    }

    float m_i[4], l_i[4];
    u64 acc2[4][4];
#pragma unroll
    for (int i = 0; i < 4; i++) {
        m_i[i] = -1e30f; l_i[i] = 0.f;
#pragma unroll
        for (int j = 0; j < 4; j++) acc2[i][j] = 0ULL;
    }
    __syncthreads();

    for (int kt = 0; kt < NS / 64; kt++) {
        const int k0 = kt * 64;
        for (int i = tid; i < 64 * 16; i += 128) {
            int row = i >> 4, c4 = (i & 15) * 4;
            *(float4*)&Ks[row * 68 + c4] =
                *(const float4*)&g_k[base + (size_t)(k0 + row) * HD + c4];
            *(float4*)&Vs[row * 68 + c4] =
                *(const float4*)&g_v[base + (size_t)(k0 + row) * HD + c4];
        }
        if (tid < 64) mk[tid] = mask[b * NS + k0 + tid];
        __syncthreads();

        // ---- S = Q K^T  (FFMA2 packed along d) ----
        u64 s2[4][8];
#pragma unroll
        for (int i = 0; i < 4; i++)
#pragma unroll
            for (int j = 0; j < 8; j++) s2[i][j] = 0ULL;
#pragma unroll 4
        for (int c4 = 0; c4 < HD; c4 += 4) {
            ulonglong2 aq[4], bk[8];
#pragma unroll
            for (int i = 0; i < 4; i++)
                aq[i] = *(const ulonglong2*)&Qs[(ty * 4 + i) * 68 + c4];
#pragma unroll
            for (int j = 0; j < 8; j++)
                bk[j] = *(const ulonglong2*)&Ks[(tx + 8 * j) * 68 + c4];
#pragma unroll
            for (int i = 0; i < 4; i++)
#pragma unroll
                for (int j = 0; j < 8; j++) {
                    fma2(s2[i][j], aq[i].x, bk[j].x);
                    fma2(s2[i][j], aq[i].y, bk[j].y);
                }
        }
        float s[4][8];
#pragma unroll
        for (int i = 0; i < 4; i++)
#pragma unroll
            for (int j = 0; j < 8; j++) {
                float2 p = unpack2(s2[i][j]);
                s[i][j] = p.x + p.y;
            }

        // ---- relative bias + mask ----
        const int dt = qt - kt;
        if (dt >= 2) {
#pragma unroll
            for (int i = 0; i < 4; i++)
#pragma unroll
                for (int j = 0; j < 8; j++) s[i][j] += qe128[i] + mk[tx + 8 * j];
        } else if (dt <= -2) {
#pragma unroll
            for (int i = 0; i < 4; i++)
#pragma unroll
                for (int j = 0; j < 8; j++) s[i][j] += qe0[i] + mk[tx + 8 * j];
        } else {
#pragma unroll
            for (int i = 0; i < 4; i++) {
                int qg = q0 + ty * 4 + i;
                const float* qer = &g_qe[((size_t)bh * NS + qg) * NR];
#pragma unroll
                for (int j = 0; j < 8; j++) {
                    int kg = k0 + tx + 8 * j;
                    int rp = qg - kg;
                    rp = rp < -64 ? -64 : (rp > 64 ? 64 : rp);
                    s[i][j] += __ldg(&qer[rp + 64]) + mk[tx + 8 * j];
                }
            }
        }

        // ---- streaming softmax ----
        float c[4], rstile[4], em[4];
#pragma unroll
        for (int i = 0; i < 4; i++) {
            float rmax = s[i][0];
#pragma unroll
            for (int j = 1; j < 8; j++) rmax = fmaxf(rmax, s[i][j]);
#pragma unroll
            for (int o = 1; o < 8; o <<= 1)
                rmax = fmaxf(rmax, __shfl_xor_sync(0xffffffffu, rmax, o));
            float mn = fmaxf(m_i[i], rmax);
            c[i] = __expf(m_i[i] - mn);
            m_i[i] = mn;
            em[i] = __expf(mn);            // abs-scale for pw (scores bounded)
            float rs = 0.f;
#pragma unroll
            for (int j = 0; j < 8; j++) { s[i][j] = __expf(s[i][j] - mn); rs += s[i][j]; }
#pragma unroll
            for (int o = 1; o < 8; o <<= 1) rs += __shfl_xor_sync(0xffffffffu, rs, o);
            l_i[i] = l_i[i] * c[i] + rs;
            rstile[i] = rs;
            u64 cd = dup2(c[i]);
#pragma unroll
            for (int j = 0; j < 4; j++) mul2(acc2[i][j], cd);
        }

        // stage P transposed [key][q]
#pragma unroll
        for (int i = 0; i < 4; i++)
#pragma unroll
            for (int j = 0; j < 8; j++)
                Pt[(tx + 8 * j) * 68 + ty * 4 + i] = s[i][j];

        // ---- bucket-probability accumulation (ABSOLUTE exp units) ----
        if (dt >= 2) {
            if (tx == 0)
#pragma unroll
                for (int i = 0; i < 4; i++)
                    pwt[128 * 68 + ty * 4 + i] += rstile[i] * em[i];
        } else if (dt <= -2) {
            if (tx == 0)
#pragma unroll
                for (int i = 0; i < 4; i++)
                    pwt[0 * 68 + ty * 4 + i] += rstile[i] * em[i];
        } else if (dt == -1) {
#pragma unroll
            for (int i = 0; i < 4; i++) {
                int qg = q0 + ty * 4 + i;
                float csum = 0.f;
#pragma unroll
                for (int j = 0; j < 8; j++) {
                    int kg = k0 + tx + 8 * j;
                    int rp = qg - kg;
                    float ps = s[i][j] * em[i];
                    if (rp <= -64) csum += ps;
                    else pwt[(rp + 64) * 68 + ty * 4 + i] += ps;
                }
#pragma unroll
                for (int o = 1; o < 8; o <<= 1)
                    csum += __shfl_xor_sync(0xffffffffu, csum, o);
                if (tx == 0) pwt[0 * 68 + ty * 4 + i] += csum;
            }
        } else if (dt == 1) {
#pragma unroll
            for (int i = 0; i < 4; i++) {
                int qg = q0 + ty * 4 + i;
                float csum = 0.f;
#pragma unroll
                for (int j = 0; j < 8; j++) {
                    int kg = k0 + tx + 8 * j;
                    int rp = qg - kg;
                    float ps = s[i][j] * em[i];
                    if (rp >= 64) csum += ps;
                    else pwt[(rp + 64) * 68 + ty * 4 + i] += ps;
                }
#pragma unroll
                for (int o = 1; o < 8; o <<= 1)
                    csum += __shfl_xor_sync(0xffffffffu, csum, o);
                if (tx == 0) pwt[128 * 68 + ty * 4 + i] += csum;
            }
        } else {
#pragma unroll
            for (int i = 0; i < 4; i++) {
                int qg = q0 + ty * 4 + i;
#pragma unroll
                for (int j = 0; j < 8; j++) {
                    int kg = k0 + tx + 8 * j;
                    int rp = qg - kg;
                    pwt[(rp + 64) * 68 + ty * 4 + i] += s[i][j] * em[i];
                }
            }
        }
        __syncthreads();   // Pt visible to all before PV

        // ---- O += P V  (FFMA2 packed along d) ----
#pragma unroll 4
        for (int k = 0; k < 64; k++) {
            float4 p4 = *(const float4*)&Pt[k * 68 + ty * 4];
            ulonglong2 v0 = *(const ulonglong2*)&Vs[k * 68 + tx * 8];
            ulonglong2 v1 = *(const ulonglong2*)&Vs[k * 68 + tx * 8 + 4];
            u64 vv[4] = {v0.x, v0.y, v1.x, v1.y};
            u64 pd[4] = {dup2(p4.x), dup2(p4.y), dup2(p4.z), dup2(p4.w)};
#pragma unroll
            for (int i = 0; i < 4; i++)
#pragma unroll
                for (int j = 0; j < 4; j++) fma2(acc2[i][j], pd[i], vv[j]);
        }
        __syncthreads();   // before next tile overwrites Ks/Vs; orders pw RMW
    }

    // ---- epilogue: ctx_rel = pw @ emb_v ----
    float* evs = Qs;   // 129*64 = 8256 floats <= 8704 (Qs+Ks)
    for (int i = tid; i < NR * HD; i += 128) evs[i] = emb_v[i];
    __syncthreads();

    u64 rel2[4][4];
#pragma unroll
    for (int i = 0; i < 4; i++)
#pragma unroll
        for (int j = 0; j < 4; j++) rel2[i][j] = 0ULL;
#pragma unroll 4
    for (int r = 0; r < NR; r++) {
        float4 p4 = *(const float4*)&pwt[r * 68 + ty * 4];
        ulonglong2 e0 = *(const ulonglong2*)&evs[r * HD + tx * 8];
        ulonglong2 e1 = *(const ulonglong2*)&evs[r * HD + tx * 8 + 4];
        u64 ev[4] = {e0.x, e0.y, e1.x, e1.y};
        u64 pd[4] = {dup2(p4.x), dup2(p4.y), dup2(p4.z), dup2(p4.w)};
#pragma unroll
        for (int i = 0; i < 4; i++)
#pragma unroll
            for (int j = 0; j < 4; j++) fma2(rel2[i][j], pd[i], ev[j]);
    }

#pragma unroll
    for (int i = 0; i < 4; i++) {
        int qg = q0 + ty * 4 + i;
        float inv = 1.0f / l_i[i];
        float emf = __expf(-m_i[i]);       // undo absolute scale on pw
        float* op = &out[((size_t)(b * NS + qg)) * ND + h * HD + tx * 8];
        float o[8];
#pragma unroll
        for (int j = 0; j < 4; j++) {
            float2 a = unpack2(acc2[i][j]);
            float2 rl = unpack2(rel2[i][j]);
            o[j * 2 + 0] = (a.x + rl.x * emf) * inv;
            o[j * 2 + 1] = (a.y + rl.y * emf) * inv;
        }
        *(float4*)&op[0] = make_float4(o[0], o[1], o[2], o[3]);
        *(float4*)&op[4] = make_float4(o[4], o[5], o[6], o[7]);
    }
}

// ---------------------------------------------------------------------------
extern "C" void kernel_launch(void* const* d_in, const int* in_sizes, int n_in,
                              void* d_out, int out_size)
{
    const float* hid   = (const float*)d_in[0];
    const float* mask  = (const float*)d_in[1];
    const float* Wq    = (const float*)d_in[2];
    const float* bq    = (const float*)d_in[3];
    const float* Wk    = (const float*)d_in[4];
    const float* bk    = (const float*)d_in[5];
    const float* Wv    = (const float*)d_in[6];
    const float* bv    = (const float*)d_in[7];
    const float* emb_k = (const float*)d_in[8];
    const float* emb_v = (const float*)d_in[9];
    float* out = (float*)d_out;

    dim3 g1(ND / 128, (NB * NS) / 128, 3);
    qkv_kernel<<<g1, 256>>>(hid, Wq, bq, Wk, bk, Wv, bv);

    qe_kernel<<<(NB * NH * NS) / 32, 128>>>(emb_k);

    size_t smem = (size_t)(4 * 64 * 68 + NR * 68 + 64) * sizeof(float);
    cudaFuncSetAttribute(attn_kernel, cudaFuncAttributeMaxDynamicSharedMemorySize,
                         (int)smem);
    attn_kernel<<<dim3(NS / 64, NB * NH), 128, smem>>>(mask, emb_v, out);
}

// round 10
// speedup vs baseline: 1.3751x; 1.1340x over previous
#include <cuda_runtime.h>
#include <cstdint>

#define NB 2
#define NS 2048
#define ND 1024
#define NH 16
#define HD 64
#define NR 129   // 2*64+1 relative buckets

typedef unsigned long long u64;

__device__ __forceinline__ void fma2(u64& d, u64 a, u64 b) {
    asm("fma.rn.f32x2 %0, %1, %2, %0;" : "+l"(d) : "l"(a), "l"(b));
}
__device__ __forceinline__ void mul2(u64& d, u64 a) {
    asm("mul.rn.f32x2 %0, %0, %1;" : "+l"(d) : "l"(a));
}
__device__ __forceinline__ u64 dup2(float x) {
    u64 o; unsigned r = __float_as_uint(x);
    asm("mov.b64 %0, {%1, %1};" : "=l"(o) : "r"(r));
    return o;
}
__device__ __forceinline__ float2 unpack2(u64 v) {
    unsigned lo, hi;
    asm("mov.b64 {%0, %1}, %2;" : "=r"(lo), "=r"(hi) : "l"(v));
    return make_float2(__uint_as_float(lo), __uint_as_float(hi));
}
__device__ __forceinline__ void cpa16(uint32_t s, const void* g) {
    asm volatile("cp.async.cg.shared.global [%0], [%1], 16;" :: "r"(s), "l"(g));
}
__device__ __forceinline__ void cp_commit() {
    asm volatile("cp.async.commit_group;");
}
__device__ __forceinline__ void cp_wait0() {
    asm volatile("cp.async.wait_group 0;");
}
__device__ __forceinline__ uint32_t smem_u32(const void* p) {
    return (uint32_t)__cvta_generic_to_shared(p);
}

// scratch (allocation-free rule: device globals)
__device__ float g_q[(size_t)NB * NH * NS * HD];   // pre-scaled by 1/sqrt(d)
__device__ float g_k[(size_t)NB * NH * NS * HD];
__device__ float g_v[(size_t)NB * NH * NS * HD];
__device__ float g_qe[(size_t)NB * NH * NS * NR];  // q . emb_k[r], scale folded in

// ---------------------------------------------------------------------------
// Kernel 1: fused QKV projection. 128x128 tile, BK=16, double-buffered smem,
// one barrier per step, B staged via cp.async (2 chunks/thread), FFMA2.
// ---------------------------------------------------------------------------
#define QBK 16
__global__ __launch_bounds__(256) void qkv_kernel(
    const float* __restrict__ hid,
    const float* __restrict__ Wq, const float* __restrict__ bq,
    const float* __restrict__ Wk, const float* __restrict__ bk,
    const float* __restrict__ Wv, const float* __restrict__ bv)
{
    const int bz = blockIdx.z;
    const float* W    = (bz == 0) ? Wq : (bz == 1) ? Wk : Wv;
    const float* bias = (bz == 0) ? bq : (bz == 1) ? bk : bv;
    float* out        = (bz == 0) ? g_q : (bz == 1) ? g_k : g_v;
    const float sc    = (bz == 0) ? 0.125f : 1.0f;   // 1/sqrt(64)

    __shared__ __align__(16) float As[2][QBK][132];   // [k][m]
    __shared__ __align__(16) float Bs[2][QBK][132];   // [k][n]

    const int tid = threadIdx.x;
    const int tx = tid & 15, ty = tid >> 4;
    const int m0 = blockIdx.y * 128, n0 = blockIdx.x * 128;

    const int arow = tid >> 1;            // 0..127 (m)
    const int acol = (tid & 1) * 8;       // k offset 0 or 8
    const int brow = tid >> 4;            // 0..15 (k)
    const int bc8  = (tid & 15) * 8;      // n offset, 8 floats via 2 cpa16

    u64 acc2[8][4];
#pragma unroll
    for (int i = 0; i < 8; i++)
#pragma unroll
        for (int j = 0; j < 4; j++) acc2[i][j] = 0ULL;

    // ---- prologue: stage tile 0 into buffer 0 ----
    {
        float4 a0 = *(const float4*)&hid[(size_t)(m0 + arow) * ND + acol];
        float4 a1 = *(const float4*)&hid[(size_t)(m0 + arow) * ND + acol + 4];
        As[0][acol + 0][arow] = a0.x; As[0][acol + 1][arow] = a0.y;
        As[0][acol + 2][arow] = a0.z; As[0][acol + 3][arow] = a0.w;
        As[0][acol + 4][arow] = a1.x; As[0][acol + 5][arow] = a1.y;
        As[0][acol + 6][arow] = a1.z; As[0][acol + 7][arow] = a1.w;
        cpa16(smem_u32(&Bs[0][brow][bc8]),     &W[(size_t)brow * ND + n0 + bc8]);
        cpa16(smem_u32(&Bs[0][brow][bc8 + 4]), &W[(size_t)brow * ND + n0 + bc8 + 4]);
        cp_commit();
        cp_wait0();
    }
    __syncthreads();

    int buf = 0;
    for (int k0 = 0; k0 < ND; k0 += QBK) {
        const bool more = (k0 + QBK) < ND;
        float4 a_n0, a_n1;
        if (more) {
            a_n0 = *(const float4*)&hid[(size_t)(m0 + arow) * ND + k0 + QBK + acol];
            a_n1 = *(const float4*)&hid[(size_t)(m0 + arow) * ND + k0 + QBK + acol + 4];
            cpa16(smem_u32(&Bs[buf ^ 1][brow][bc8]),
                  &W[(size_t)(k0 + QBK + brow) * ND + n0 + bc8]);
            cpa16(smem_u32(&Bs[buf ^ 1][brow][bc8 + 4]),
                  &W[(size_t)(k0 + QBK + brow) * ND + n0 + bc8 + 4]);
            cp_commit();
        }
#pragma unroll
        for (int kk = 0; kk < QBK; kk++) {
            float4 a0 = *(const float4*)&As[buf][kk][ty * 8];
            float4 a1 = *(const float4*)&As[buf][kk][ty * 8 + 4];
            ulonglong2 bl0 = *(const ulonglong2*)&Bs[buf][kk][tx * 8];
            ulonglong2 bl1 = *(const ulonglong2*)&Bs[buf][kk][tx * 8 + 4];
            u64 bvp[4] = {bl0.x, bl0.y, bl1.x, bl1.y};
            float av[8] = {a0.x, a0.y, a0.z, a0.w, a1.x, a1.y, a1.z, a1.w};
#pragma unroll
            for (int i = 0; i < 8; i++) {
                u64 ad = dup2(av[i]);
#pragma unroll
                for (int j = 0; j < 4; j++) fma2(acc2[i][j], ad, bvp[j]);
            }
        }
        if (more) {
            int nb = buf ^ 1;
            As[nb][acol + 0][arow] = a_n0.x; As[nb][acol + 1][arow] = a_n0.y;
            As[nb][acol + 2][arow] = a_n0.z; As[nb][acol + 3][arow] = a_n0.w;
            As[nb][acol + 4][arow] = a_n1.x; As[nb][acol + 5][arow] = a_n1.y;
            As[nb][acol + 6][arow] = a_n1.z; As[nb][acol + 7][arow] = a_n1.w;
            cp_wait0();
        }
        __syncthreads();
        buf ^= 1;
    }

#pragma unroll
    for (int i = 0; i < 8; i++) {
        int m = m0 + ty * 8 + i;           // m = b*S + s
        int b = m >> 11, s = m & (NS - 1);
#pragma unroll
        for (int jj = 0; jj < 2; jj++) {
            int n = n0 + tx * 8 + jj * 4;  // n = h*64 + d
            int h = n >> 6, dd = n & 63;
            float2 p0 = unpack2(acc2[i][jj * 2 + 0]);
            float2 p1 = unpack2(acc2[i][jj * 2 + 1]);
            float4 o;
            o.x = (p0.x + bias[n + 0]) * sc;
            o.y = (p0.y + bias[n + 1]) * sc;
            o.z = (p1.x + bias[n + 2]) * sc;
            o.w = (p1.y + bias[n + 3]) * sc;
            *(float4*)&out[(((size_t)(b * NH + h) * NS) + s) * HD + dd] = o;
        }
    }
}

// ---------------------------------------------------------------------------
// Kernel 2: qe[g][r] = sum_d g_q[g][d] * emb_k[r][d]
// ---------------------------------------------------------------------------
__global__ __launch_bounds__(128) void qe_kernel(const float* __restrict__ emb_k)
{
    __shared__ float eks[NR * 65];
    __shared__ float qs[32 * 65];
    const int tid = threadIdx.x;
    const size_t g0 = (size_t)blockIdx.x * 32;

    for (int i = tid; i < NR * HD; i += 128) {
        int r = i >> 6, d = i & 63;
        eks[r * 65 + d] = emb_k[i];
    }
    for (int i = tid; i < 32 * HD; i += 128) {
        int ql = i >> 6, d = i & 63;
        qs[ql * 65 + d] = g_q[(g0 + ql) * HD + d];
    }
    __syncthreads();

    for (int i = tid; i < 32 * NR; i += 128) {
        int ql = i / NR, r = i - ql * NR;
        float s = 0.f;
#pragma unroll
        for (int d = 0; d < HD; d++) s += qs[ql * 65 + d] * eks[r * 65 + d];
        g_qe[(g0 + ql) * NR + r] = s;
    }
}

// ---------------------------------------------------------------------------
// Kernel 3: flash attention w/ relative bias & value buckets.
// FFMA2 packed; cp.async staging; conflict-free V/emb_v columns.
// pw in absolute exp units.
// ---------------------------------------------------------------------------
__global__ __launch_bounds__(128) void attn_kernel(
    const float* __restrict__ mask, const float* __restrict__ emb_v,
    float* __restrict__ out)
{
    extern __shared__ float sm[];
    float* Qs   = sm;                    // [64][68]
    float* Ks   = Qs + 64 * 68;          // [64][68]
    float* Vs   = Ks + 64 * 68;          // [64][68]
    float* Pt   = Vs + 64 * 68;          // [key][q] 64x68
    float* pwt  = Pt + 64 * 68;          // [129][68]  (r-major, q minor)
    float* mk   = pwt + NR * 68;         // [64]

    const int tid = threadIdx.x;
    const int tx = tid & 7, ty = tid >> 3;          // ty in [0,16)
    const int qt = blockIdx.x, bh = blockIdx.y;
    const int b = bh >> 4, h = bh & 15;
    const size_t base = (size_t)bh * NS * HD;
    const int q0 = qt * 64;

    const int srow = tid >> 4;            // staging: 8 rows per pass
    const int sc4  = (tid & 15) * 4;      // 16B chunk

    // stage Q tile (cp.async) + zero pwt
    for (int r8 = 0; r8 < 64; r8 += 8)
        cpa16(smem_u32(&Qs[(r8 + srow) * 68 + sc4]),
              &g_q[base + (size_t)(q0 + r8 + srow) * HD + sc4]);
    cp_commit();
    for (int i = tid; i < NR * 68; i += 128) pwt[i] = 0.f;

    float qe0[4], qe128[4];
    const size_t qeb = ((size_t)bh * NS + q0) * NR;
#pragma unroll
    for (int i = 0; i < 4; i++) {
        int q = ty * 4 + i;
        qe0[i]   = g_qe[qeb + (size_t)q * NR + 0];
        qe128[i] = g_qe[qeb + (size_t)q * NR + 128];
    }

    float m_i[4], l_i[4];
    u64 acc2[4][4];
#pragma unroll
    for (int i = 0; i < 4; i++) {
        m_i[i] = -1e30f; l_i[i] = 0.f;
#pragma unroll
        for (int j = 0; j < 4; j++) acc2[i][j] = 0ULL;
    }
    cp_wait0();
    __syncthreads();

    for (int kt = 0; kt < NS / 64; kt++) {
        const int k0 = kt * 64;
        // stage K/V via cp.async (prev-tile barrier protects buffers)
        for (int r8 = 0; r8 < 64; r8 += 8) {
            cpa16(smem_u32(&Ks[(r8 + srow) * 68 + sc4]),
                  &g_k[base + (size_t)(k0 + r8 + srow) * HD + sc4]);
            cpa16(smem_u32(&Vs[(r8 + srow) * 68 + sc4]),
                  &g_v[base + (size_t)(k0 + r8 + srow) * HD + sc4]);
        }
        cp_commit();
        if (tid < 64) mk[tid] = mask[b * NS + k0 + tid];
        cp_wait0();
        __syncthreads();

        // ---- S = Q K^T  (FFMA2 packed along d) ----
        u64 s2[4][8];
#pragma unroll
        for (int i = 0; i < 4; i++)
#pragma unroll
            for (int j = 0; j < 8; j++) s2[i][j] = 0ULL;
#pragma unroll 4
        for (int c4 = 0; c4 < HD; c4 += 4) {
            ulonglong2 aq[4], bk[8];
#pragma unroll
            for (int i = 0; i < 4; i++)
                aq[i] = *(const ulonglong2*)&Qs[(ty * 4 + i) * 68 + c4];
#pragma unroll
            for (int j = 0; j < 8; j++)
                bk[j] = *(const ulonglong2*)&Ks[(tx + 8 * j) * 68 + c4];
#pragma unroll
            for (int i = 0; i < 4; i++)
#pragma unroll
                for (int j = 0; j < 8; j++) {
                    fma2(s2[i][j], aq[i].x, bk[j].x);
                    fma2(s2[i][j], aq[i].y, bk[j].y);
                }
        }
        float s[4][8];
#pragma unroll
        for (int i = 0; i < 4; i++)
#pragma unroll
            for (int j = 0; j < 8; j++) {
                float2 p = unpack2(s2[i][j]);
                s[i][j] = p.x + p.y;
            }

        // ---- relative bias + mask ----
        const int dt = qt - kt;
        if (dt >= 2) {
#pragma unroll
            for (int i = 0; i < 4; i++)
#pragma unroll
                for (int j = 0; j < 8; j++) s[i][j] += qe128[i] + mk[tx + 8 * j];
        } else if (dt <= -2) {
#pragma unroll
            for (int i = 0; i < 4; i++)
#pragma unroll
                for (int j = 0; j < 8; j++) s[i][j] += qe0[i] + mk[tx + 8 * j];
        } else {
#pragma unroll
            for (int i = 0; i < 4; i++) {
                int qg = q0 + ty * 4 + i;
                const float* qer = &g_qe[((size_t)bh * NS + qg) * NR];
#pragma unroll
                for (int j = 0; j < 8; j++) {
                    int kg = k0 + tx + 8 * j;
                    int rp = qg - kg;
                    rp = rp < -64 ? -64 : (rp > 64 ? 64 : rp);
                    s[i][j] += __ldg(&qer[rp + 64]) + mk[tx + 8 * j];
                }
            }
        }

        // ---- streaming softmax ----
        float c[4], rstile[4], em[4];
#pragma unroll
        for (int i = 0; i < 4; i++) {
            float rmax = s[i][0];
#pragma unroll
            for (int j = 1; j < 8; j++) rmax = fmaxf(rmax, s[i][j]);
#pragma unroll
            for (int o = 1; o < 8; o <<= 1)
                rmax = fmaxf(rmax, __shfl_xor_sync(0xffffffffu, rmax, o));
            float mn = fmaxf(m_i[i], rmax);
            c[i] = __expf(m_i[i] - mn);
            m_i[i] = mn;
            em[i] = __expf(mn);            // abs-scale for pw (scores bounded)
            float rs = 0.f;
#pragma unroll
            for (int j = 0; j < 8; j++) { s[i][j] = __expf(s[i][j] - mn); rs += s[i][j]; }
#pragma unroll
            for (int o = 1; o < 8; o <<= 1) rs += __shfl_xor_sync(0xffffffffu, rs, o);
            l_i[i] = l_i[i] * c[i] + rs;
            rstile[i] = rs;
            u64 cd = dup2(c[i]);
#pragma unroll
            for (int j = 0; j < 4; j++) mul2(acc2[i][j], cd);
        }

        // stage P transposed [key][q]
#pragma unroll
        for (int i = 0; i < 4; i++)
#pragma unroll
            for (int j = 0; j < 8; j++)
                Pt[(tx + 8 * j) * 68 + ty * 4 + i] = s[i][j];

        // ---- bucket-probability accumulation (ABSOLUTE exp units) ----
        if (dt >= 2) {
            if (tx == 0)
#pragma unroll
                for (int i = 0; i < 4; i++)
                    pwt[128 * 68 + ty * 4 + i] += rstile[i] * em[i];
        } else if (dt <= -2) {
            if (tx == 0)
#pragma unroll
                for (int i = 0; i < 4; i++)
                    pwt[0 * 68 + ty * 4 + i] += rstile[i] * em[i];
        } else if (dt == -1) {
#pragma unroll
            for (int i = 0; i < 4; i++) {
                int qg = q0 + ty * 4 + i;
                float csum = 0.f;
#pragma unroll
                for (int j = 0; j < 8; j++) {
                    int kg = k0 + tx + 8 * j;
                    int rp = qg - kg;
                    float ps = s[i][j] * em[i];
                    if (rp <= -64) csum += ps;
                    else pwt[(rp + 64) * 68 + ty * 4 + i] += ps;
                }
#pragma unroll
                for (int o = 1; o < 8; o <<= 1)
                    csum += __shfl_xor_sync(0xffffffffu, csum, o);
                if (tx == 0) pwt[0 * 68 + ty * 4 + i] += csum;
            }
        } else if (dt == 1) {
#pragma unroll
            for (int i = 0; i < 4; i++) {
                int qg = q0 + ty * 4 + i;
                float csum = 0.f;
#pragma unroll
                for (int j = 0; j < 8; j++) {
                    int kg = k0 + tx + 8 * j;
                    int rp = qg - kg;
                    float ps = s[i][j] * em[i];
                    if (rp >= 64) csum += ps;
                    else pwt[(rp + 64) * 68 + ty * 4 + i] += ps;
                }
#pragma unroll
                for (int o = 1; o < 8; o <<= 1)
                    csum += __shfl_xor_sync(0xffffffffu, csum, o);
                if (tx == 0) pwt[128 * 68 + ty * 4 + i] += csum;
            }
        } else {
#pragma unroll
            for (int i = 0; i < 4; i++) {
                int qg = q0 + ty * 4 + i;
#pragma unroll
                for (int j = 0; j < 8; j++) {
                    int kg = k0 + tx + 8 * j;
                    int rp = qg - kg;
                    pwt[(rp + 64) * 68 + ty * 4 + i] += s[i][j] * em[i];
                }
            }
        }
        __syncthreads();   // Pt visible to all before PV

        // ---- O += P V  (d-cols tx*4 and 32+tx*4: conflict-free) ----
#pragma unroll 4
        for (int k = 0; k < 64; k++) {
            float4 p4 = *(const float4*)&Pt[k * 68 + ty * 4];
            ulonglong2 v0 = *(const ulonglong2*)&Vs[k * 68 + tx * 4];
            ulonglong2 v1 = *(const ulonglong2*)&Vs[k * 68 + 32 + tx * 4];
            u64 vv[4] = {v0.x, v0.y, v1.x, v1.y};
            u64 pd[4] = {dup2(p4.x), dup2(p4.y), dup2(p4.z), dup2(p4.w)};
#pragma unroll
            for (int i = 0; i < 4; i++)
#pragma unroll
                for (int j = 0; j < 4; j++) fma2(acc2[i][j], pd[i], vv[j]);
        }
        __syncthreads();   // before next tile overwrites Ks/Vs; orders pw RMW
    }

    // ---- epilogue: ctx_rel = pw @ emb_v ----
    float* evs = Qs;   // 129*64 = 8256 floats <= 8704 (Qs+Ks)
    for (int i = tid; i < NR * HD; i += 128) evs[i] = emb_v[i];
    __syncthreads();

    u64 rel2[4][4];
#pragma unroll
    for (int i = 0; i < 4; i++)
#pragma unroll
        for (int j = 0; j < 4; j++) rel2[i][j] = 0ULL;
#pragma unroll 4
    for (int r = 0; r < NR; r++) {
        float4 p4 = *(const float4*)&pwt[r * 68 + ty * 4];
        ulonglong2 e0 = *(const ulonglong2*)&evs[r * HD + tx * 4];
        ulonglong2 e1 = *(const ulonglong2*)&evs[r * HD + 32 + tx * 4];
        u64 ev[4] = {e0.x, e0.y, e1.x, e1.y};
        u64 pd[4] = {dup2(p4.x), dup2(p4.y), dup2(p4.z), dup2(p4.w)};
#pragma unroll
        for (int i = 0; i < 4; i++)
#pragma unroll
            for (int j = 0; j < 4; j++) fma2(rel2[i][j], pd[i], ev[j]);
    }

#pragma unroll
    for (int i = 0; i < 4; i++) {
        int qg = q0 + ty * 4 + i;
        float inv = 1.0f / l_i[i];
        float emf = __expf(-m_i[i]);       // undo absolute scale on pw
        float* op = &out[((size_t)(b * NS + qg)) * ND + h * HD];
        float o[8];
#pragma unroll
        for (int j = 0; j < 4; j++) {
            float2 a = unpack2(acc2[i][j]);
            float2 rl = unpack2(rel2[i][j]);
            o[j * 2 + 0] = (a.x + rl.x * emf) * inv;
            o[j * 2 + 1] = (a.y + rl.y * emf) * inv;
        }
        *(float4*)&op[tx * 4]      = make_float4(o[0], o[1], o[2], o[3]);
        *(float4*)&op[32 + tx * 4] = make_float4(o[4], o[5], o[6], o[7]);
    }
}

// ---------------------------------------------------------------------------
extern "C" void kernel_launch(void* const* d_in, const int* in_sizes, int n_in,
                              void* d_out, int out_size)
{
    const float* hid   = (const float*)d_in[0];
    const float* mask  = (const float*)d_in[1];
    const float* Wq    = (const float*)d_in[2];
    const float* bq    = (const float*)d_in[3];
    const float* Wk    = (const float*)d_in[4];
    const float* bk    = (const float*)d_in[5];
    const float* Wv    = (const float*)d_in[6];
    const float* bv    = (const float*)d_in[7];
    const float* emb_k = (const float*)d_in[8];
    const float* emb_v = (const float*)d_in[9];
    float* out = (float*)d_out;

    dim3 g1(ND / 128, (NB * NS) / 128, 3);
    qkv_kernel<<<g1, 256>>>(hid, Wq, bq, Wk, bk, Wv, bv);

    qe_kernel<<<(NB * NH * NS) / 32, 128>>>(emb_k);

    size_t smem = (size_t)(4 * 64 * 68 + NR * 68 + 64) * sizeof(float);
    cudaFuncSetAttribute(attn_kernel, cudaFuncAttributeMaxDynamicSharedMemorySize,
                         (int)smem);
    attn_kernel<<<dim3(NS / 64, NB * NH), 128, smem>>>(mask, emb_v, out);
}